// round 15
// baseline (speedup 1.0000x reference)
#include <cuda_runtime.h>
#include <cstdint>

// ---------------------------------------------------------------------------
// MPNEncoder, DEPTH=6, H=128 — bf16 hi/lo split GEMMs on legacy HMMA
// (mma.sync.m16n8k16.bf16; tcgen05 is PTX-gated off under compute_103).
//
//   attnei[a]  = sum_j attfea[a2attached[a,j]]             (once)
//   k_bias (fused, 2 phases sharing fp32 accum, 128-row tiles):
//     phase0: acc  = init_messages @ W_i ; msg0 = relu(acc)
//     phase1: acc += (attnei[b2a]-attfea[b2a_rev]) @ W_h[128:] ; bias = acc
//   5x: nei[a] = sum_j msg[a2nei[a,j]]
//       msg    = relu(bias + (nei[b2a] - msg[b2revb]) @ W_h[:128])
//
// R14: k_msg becomes a cp.async double-buffered gather pipeline — raw
// nei/msg rows for tile t+1 stream into smem during tile t's MMA; the
// A-fill is an smem->smem convert (no exposed LDG latency).  1 CTA/SM,
// 224KB smem, grid 152.
// ---------------------------------------------------------------------------

constexpr int NBb  = 500000;
constexpr int NAa  = 250000;
constexpr int DMSG = 165;
constexpr int DATT = 151;
constexpr int HH   = 128;

constexpr int K_WI  = 176;
constexpr int K_ATT = 160;
constexpr int K_MSG = 128;
constexpr int BROWS = K_WI + K_ATT + K_MSG;          // 464

constexpr int NT64 = (NBb + 63) / 64;                // 7813 64-row tiles
constexpr int NSM  = 152;

__device__ float g_bias2 [(size_t)NBb * HH];
__device__ float g_msg0  [(size_t)NBb * HH];
__device__ float g_msg1  [(size_t)NBb * HH];
__device__ float g_nei   [(size_t)NAa * HH];
__device__ float g_attnei[(size_t)NAa * DATT];
__device__ uint4 g_B     [BROWS * 32];               // 464*512 bytes

typedef unsigned int u32;

__device__ __forceinline__ u32 smem_u32(const void* p) {
    u32 a;
    asm("{ .reg .u64 t; cvta.to.shared.u64 t, %1; cvt.u32.u64 %0, t; }"
        : "=r"(a) : "l"(p));
    return a;
}
__device__ __forceinline__ void ldmx4(u32& r0, u32& r1, u32& r2, u32& r3, u32 addr) {
    asm volatile("ldmatrix.sync.aligned.m8n8.x4.shared.b16 {%0,%1,%2,%3}, [%4];"
                 : "=r"(r0), "=r"(r1), "=r"(r2), "=r"(r3) : "r"(addr));
}
__device__ __forceinline__ void ldmx4t(u32& r0, u32& r1, u32& r2, u32& r3, u32 addr) {
    asm volatile("ldmatrix.sync.aligned.m8n8.x4.trans.shared.b16 {%0,%1,%2,%3}, [%4];"
                 : "=r"(r0), "=r"(r1), "=r"(r2), "=r"(r3) : "r"(addr));
}
__device__ __forceinline__ void mma_bf16(float (&d)[4],
                                         u32 a0, u32 a1, u32 a2, u32 a3,
                                         u32 b0, u32 b1) {
    asm volatile("mma.sync.aligned.m16n8k16.row.col.f32.bf16.bf16.f32 "
                 "{%0,%1,%2,%3}, {%4,%5,%6,%7}, {%8,%9}, {%0,%1,%2,%3};"
                 : "+f"(d[0]), "+f"(d[1]), "+f"(d[2]), "+f"(d[3])
                 : "r"(a0), "r"(a1), "r"(a2), "r"(a3), "r"(b0), "r"(b1));
}
__device__ __forceinline__ void cpasync16(u32 dst, const void* src) {
    asm volatile("cp.async.cg.shared.global [%0], [%1], 16;"
                 :: "r"(dst), "l"(src));
}
__device__ __forceinline__ void cp_commit() {
    asm volatile("cp.async.commit_group;" ::: "memory");
}
__device__ __forceinline__ void cp_wait1() {
    asm volatile("cp.async.wait_group 1;" ::: "memory");
}
__device__ __forceinline__ void cpasync_wait() {
    asm volatile("cp.async.commit_group;\ncp.async.wait_group 0;" ::: "memory");
}

// 8 floats -> 4 hi bf16x2 regs + 4 lo bf16x2 regs (low half = even index)
__device__ __forceinline__ void cvt8(const float* v, u32* hi, u32* lo) {
    #pragma unroll
    for (int i = 0; i < 4; ++i) {
        u32 u0 = __float_as_uint(v[2 * i])     & 0xffff0000u;
        u32 u1 = __float_as_uint(v[2 * i + 1]) & 0xffff0000u;
        hi[i] = u1 | (u0 >> 16);
        float l0 = v[2 * i]     - __uint_as_float(u0);
        float l1 = v[2 * i + 1] - __uint_as_float(u1);
        asm("cvt.rn.bf16x2.f32 %0, %1, %2;" : "=r"(lo[i]) : "f"(l1), "f"(l0));
    }
}

// Shared MMA mainloop.  Warp tile (MT*16) x 32; nt = 4.  Full unroll over NK.
template<int PITCHA, int MT, int NK>
__device__ __forceinline__ void mma_loop(
    u32 uAhi, u32 uAlo, u32 uBhi, u32 uBlo,
    float (&acc)[MT][4][4], int lane, int wm, int wn)
{
    const int aj   = lane >> 3;
    const int ai   = lane & 7;
    const int ajk  = aj >> 1;
    const int ajr  = (aj & 1) * 8;
    const int bkl  = lane & 15;
    const int bchl = lane >> 4;

    #pragma unroll 2
    for (int ks = 0; ks < NK; ++ks) {
        u32 ah[MT][4], al[MT][4];
        #pragma unroll
        for (int mt = 0; mt < MT; ++mt) {
            int arow = wm * (16 * MT) + mt * 16 + ajr + ai;
            int ch   = 2 * ks + ajk;
            u32 off  = (u32)(arow * PITCHA) + (u32)((ch ^ (arow & 7)) << 4);
            ldmx4(ah[mt][0], ah[mt][1], ah[mt][2], ah[mt][3], uAhi + off);
            ldmx4(al[mt][0], al[mt][1], al[mt][2], al[mt][3], uAlo + off);
        }
        u32 bh[4][2], bl[4][2];
        #pragma unroll
        for (int nt2 = 0; nt2 < 2; ++nt2) {
            int krow = ks * 16 + bkl;
            int ch   = wn * 4 + nt2 * 2 + bchl;
            u32 off  = (u32)(krow * 256) + (u32)((ch ^ (krow & 7)) << 4);
            u32 r0, r1, r2, r3;
            ldmx4t(r0, r1, r2, r3, uBhi + off);
            bh[2 * nt2][0] = r0; bh[2 * nt2][1] = r1;
            bh[2 * nt2 + 1][0] = r2; bh[2 * nt2 + 1][1] = r3;
            ldmx4t(r0, r1, r2, r3, uBlo + off);
            bl[2 * nt2][0] = r0; bl[2 * nt2][1] = r1;
            bl[2 * nt2 + 1][0] = r2; bl[2 * nt2 + 1][1] = r3;
        }
        #pragma unroll
        for (int mt = 0; mt < MT; ++mt)
            #pragma unroll
            for (int nt = 0; nt < 4; ++nt) {
                mma_bf16(acc[mt][nt], ah[mt][0], ah[mt][1], ah[mt][2], ah[mt][3],
                         bh[nt][0], bh[nt][1]);
                mma_bf16(acc[mt][nt], ah[mt][0], ah[mt][1], ah[mt][2], ah[mt][3],
                         bl[nt][0], bl[nt][1]);
                mma_bf16(acc[mt][nt], al[mt][0], al[mt][1], al[mt][2], al[mt][3],
                         bh[nt][0], bh[nt][1]);
            }
    }
}

// ---------------------------------------------------------------------------
// k_att_agg + B-plane prep (extra blocks).
// ---------------------------------------------------------------------------
constexpr int GA = NAa / 8;                              // 31250
constexpr int PREP_ITEMS  = BROWS * 16;
constexpr int PREP_BLOCKS = (PREP_ITEMS + 255) / 256;    // 29

__global__ void __launch_bounds__(256) k_att_agg(
    const float* __restrict__ attfea, const int* __restrict__ a2att,
    float* __restrict__ attnei,
    const float* __restrict__ W_i, const float* __restrict__ W_h)
{
    if (blockIdx.x >= GA) {
        int idx = (blockIdx.x - GA) * 256 + threadIdx.x;
        if (idx >= PREP_ITEMS) return;
        int r = idx >> 4, q = idx & 15;
        const float* src; unsigned char* dst; int k, Ksz, Kact;
        unsigned char* gb = (unsigned char*)g_B;
        if (r < K_WI) {
            k = r;           Ksz = K_WI;  Kact = DMSG; src = W_i;           dst = gb;
        } else if (r < K_WI + K_ATT) {
            k = r - K_WI;    Ksz = K_ATT; Kact = DATT; src = W_h + HH * HH; dst = gb + K_WI * 512;
        } else {
            k = r - K_WI - K_ATT; Ksz = K_MSG; Kact = HH; src = W_h;        dst = gb + (K_WI + K_ATT) * 512;
        }
        float v[8];
        #pragma unroll
        for (int t = 0; t < 8; ++t) {
            int c = q * 8 + t;
            v[t] = (k < Kact) ? src[(long)k * HH + c] : 0.f;
        }
        u32 hi[4], lo[4];
        cvt8(v, hi, lo);
        int sw = (q ^ (k & 7)) * 16;
        *(uint4*)(dst + k * 256 + sw)             = make_uint4(hi[0], hi[1], hi[2], hi[3]);
        *(uint4*)(dst + Ksz * 256 + k * 256 + sw) = make_uint4(lo[0], lo[1], lo[2], lo[3]);
        return;
    }

    const int warp = threadIdx.x >> 5, lane = threadIdx.x & 31;
    const int a = blockIdx.x * 8 + warp;
    if (a >= NAa) return;
    int idx[6];
    #pragma unroll
    for (int j = 0; j < 6; ++j) idx[j] = a2att[a * 6 + j];
    float acc[5] = {0.f, 0.f, 0.f, 0.f, 0.f};
    #pragma unroll
    for (int j = 0; j < 6; ++j) {
        const float* p = attfea + (long)idx[j] * DATT;
        #pragma unroll
        for (int t = 0; t < 5; ++t) {
            int c = t * 32 + lane;
            if (c < DATT) acc[t] += p[c];
        }
    }
    float* o = attnei + (long)a * DATT;
    #pragma unroll
    for (int t = 0; t < 5; ++t) {
        int c = t * 32 + lane;
        if (c < DATT) o[c] = acc[t];
    }
}

// ---------------------------------------------------------------------------
// FUSED bias kernel (unchanged R13 form): 128-row tile, 512 threads, 4Mx4N.
// ---------------------------------------------------------------------------
__global__ void __launch_bounds__(512, 1) k_bias(
    const float* __restrict__ A0,     const float* __restrict__ attnei,
    const float* __restrict__ attfea, const int* __restrict__ b2a,
    const int* __restrict__ b2revb,
    float* __restrict__ bias_out, float* __restrict__ msg_out)
{
    constexpr int PITCHA = 384;

    extern __shared__ char sm[];
    char* pAhi = sm;
    char* pAlo = sm + 128 * PITCHA;
    char* pBhi = sm + 2 * 128 * PITCHA;
    const u32 uAhi = smem_u32(pAhi);
    const u32 uAlo = smem_u32(pAlo);
    const u32 uBhi = smem_u32(pBhi);

    const int tid  = threadIdx.x;
    const int lane = tid & 31;
    const int warp = tid >> 5;
    const int wm   = warp & 3;
    const int wn   = warp >> 2;
    const long row0 = (long)blockIdx.x * 128;
    const unsigned char* gb = (const unsigned char*)g_B;

    float acc[2][4][4];
    #pragma unroll
    for (int mt = 0; mt < 2; ++mt)
        #pragma unroll
        for (int nt = 0; nt < 4; ++nt)
            #pragma unroll
            for (int e = 0; e < 4; ++e) acc[mt][nt][e] = 0.f;

    const int gr = lane >> 2;
    const int gc = (lane & 3) * 2;

    // Phase 0: init_messages @ W_i (K=176)
    #pragma unroll
    for (int i = 0; i < 11; ++i) {
        int e = tid + i * 512;
        if (e < K_WI * 32) cpasync16(uBhi + e * 16, gb + e * 16);
    }
    {
        const int r = tid >> 2, h = tid & 3;
        const long b = row0 + r;
        const bool valid = b < NBb;
        const float* pA = A0 + (long)(valid ? b : 0) * DMSG;
        for (int q = h; q < K_WI / 8; q += 4) {
            float v[8];
            #pragma unroll
            for (int t = 0; t < 8; ++t) {
                int c = q * 8 + t;
                v[t] = (valid && c < DMSG) ? pA[c] : 0.f;
            }
            u32 hi[4], lo[4];
            cvt8(v, hi, lo);
            int sw = (q ^ (r & 7)) * 16;
            *(uint4*)(pAhi + r * PITCHA + sw) = make_uint4(hi[0], hi[1], hi[2], hi[3]);
            *(uint4*)(pAlo + r * PITCHA + sw) = make_uint4(lo[0], lo[1], lo[2], lo[3]);
        }
    }
    cpasync_wait();
    __syncthreads();
    mma_loop<PITCHA, 2, K_WI / 16>(uAhi, uAlo, uBhi, uBhi + K_WI * 256,
                                   acc, lane, wm, wn);

    #pragma unroll
    for (int mt = 0; mt < 2; ++mt)
        #pragma unroll
        for (int nt = 0; nt < 4; ++nt) {
            long r1 = row0 + wm * 32 + mt * 16 + gr;
            long r2 = r1 + 8;
            int  c  = wn * 32 + nt * 8 + gc;
            const float* a = acc[mt][nt];
            if (r1 < NBb)
                *(float2*)(msg_out + (size_t)r1 * HH + c) =
                    make_float2(fmaxf(a[0], 0.f), fmaxf(a[1], 0.f));
            if (r2 < NBb)
                *(float2*)(msg_out + (size_t)r2 * HH + c) =
                    make_float2(fmaxf(a[2], 0.f), fmaxf(a[3], 0.f));
        }
    __syncthreads();

    // Phase 1: attdiff @ W_h[128:] (K=160)
    #pragma unroll
    for (int i = 0; i < 10; ++i) {
        int e = tid + i * 512;
        if (e < K_ATT * 32) cpasync16(uBhi + e * 16, gb + K_WI * 512 + e * 16);
    }
    {
        const int r = tid >> 2, h = tid & 3;
        const long b = row0 + r;
        const bool valid = b < NBb;
        const long bc = valid ? b : 0;
        int ia = b2a[bc];
        int ir = b2a[b2revb[bc]];
        const float* pA = attnei + (long)ia * DATT;
        const float* pR = attfea + (long)ir * DATT;
        for (int q = h; q < K_ATT / 8; q += 4) {
            float v[8];
            #pragma unroll
            for (int t = 0; t < 8; ++t) {
                int c = q * 8 + t;
                v[t] = (valid && c < DATT) ? (pA[c] - pR[c]) : 0.f;
            }
            u32 hi[4], lo[4];
            cvt8(v, hi, lo);
            int sw = (q ^ (r & 7)) * 16;
            *(uint4*)(pAhi + r * PITCHA + sw) = make_uint4(hi[0], hi[1], hi[2], hi[3]);
            *(uint4*)(pAlo + r * PITCHA + sw) = make_uint4(lo[0], lo[1], lo[2], lo[3]);
        }
    }
    cpasync_wait();
    __syncthreads();
    mma_loop<PITCHA, 2, K_ATT / 16>(uAhi, uAlo, uBhi, uBhi + K_ATT * 256,
                                    acc, lane, wm, wn);

    #pragma unroll
    for (int mt = 0; mt < 2; ++mt)
        #pragma unroll
        for (int nt = 0; nt < 4; ++nt) {
            long r1 = row0 + wm * 32 + mt * 16 + gr;
            long r2 = r1 + 8;
            int  c  = wn * 32 + nt * 8 + gc;
            const float* a = acc[mt][nt];
            if (r1 < NBb)
                *(float2*)(bias_out + (size_t)r1 * HH + c) = make_float2(a[0], a[1]);
            if (r2 < NBb)
                *(float2*)(bias_out + (size_t)r2 * HH + c) = make_float2(a[2], a[3]);
        }
}

// ---------------------------------------------------------------------------
// PERSISTENT MSG GEMM with cp.async gather pipeline.
// 64-row tiles, 256 threads, 8 warps (2M x 4N), 1 CTA/SM (224KB smem).
// Smem: [B 64K][Ahi 16K][Alo 16K][raw0 64K][raw1 64K]; raw = nei(32K)+msg(32K).
// ---------------------------------------------------------------------------
__global__ void __launch_bounds__(256, 1) k_msg(
    const float* __restrict__ nei, const float* __restrict__ msg_in,
    const int* __restrict__ b2a, const int* __restrict__ b2revb,
    const float* __restrict__ bias, float* __restrict__ msg_out)
{
    constexpr int PITCHA = 256;
    constexpr int OFS_AHI = 65536;
    constexpr int OFS_ALO = 81920;
    constexpr int OFS_RAW = 98304;

    extern __shared__ char sm[];
    const u32 uB   = smem_u32(sm);
    const u32 uAhi = uB + OFS_AHI;
    const u32 uAlo = uB + OFS_ALO;

    const int tid  = threadIdx.x;
    const int lane = tid & 31;
    const int warp = tid >> 5;
    const int wm   = warp & 1;
    const int wn   = warp >> 1;
    const int r    = tid >> 2;            // row within tile (0..63)
    const int h    = tid & 3;             // quarter within row
    const unsigned char* gb = (const unsigned char*)g_B + (K_WI + K_ATT) * 512;

    const int gr = lane >> 2;
    const int gc = (lane & 3) * 2;

    // ---- B copy (once), same group as tile0's gathers ----
    #pragma unroll
    for (int i = 0; i < 16; ++i) {
        int e = tid + i * 256;
        cpasync16(uB + e * 16, gb + e * 16);
    }

    // Index load for this thread's row of a tile (clamped; LDG only).
    auto load_idx = [&](long tile, int& ia, int& ib) {
        long b = tile * 64 + r;
        long bc = (tile < NT64 && b < NBb) ? b : 0;
        ia = b2a[bc];
        ib = b2revb[bc];
    };
    // Issue raw gathers for one tile into buffer `buf` (16 cp.asyncs).
    auto issue = [&](int buf, int ia, int ib) {
        u32 baseN = uB + OFS_RAW + buf * 65536 + r * 512;
        u32 baseM = baseN + 32768;
        const char* pN = (const char*)(nei + (long)ia * HH);
        const char* pM = (const char*)(msg_in + (long)ib * HH);
        #pragma unroll
        for (int i = 0; i < 4; ++i) {
            int q  = h + 4 * i;
            int c0 = 2 * q, c1 = 2 * q + 1;
            u32 s0 = (u32)((c0 ^ (r & 7)) * 16);
            u32 s1 = (u32)((c1 ^ (r & 7)) * 16);
            cpasync16(baseN + s0, pN + c0 * 16);
            cpasync16(baseN + s1, pN + c1 * 16);
            cpasync16(baseM + s0, pM + c0 * 16);
            cpasync16(baseM + s1, pM + c1 * 16);
        }
    };

    // ---- Prologue: tile0 gathers + index prefetch for tile0+NSM ----
    const long tile0 = blockIdx.x;
    {
        int ia0, ib0;
        load_idx(tile0, ia0, ib0);
        if (tile0 < NT64) issue(0, ia0, ib0);
    }
    cp_commit();
    int iaN, ibN;
    load_idx(tile0 + NSM, iaN, ibN);

    int iter = 0;
    for (long tile = tile0; tile < NT64; tile += NSM, ++iter) {
        const int buf = iter & 1;
        const long row0 = tile * 64;

        // ---- Issue next tile's gathers; prefetch indices 2 tiles ahead ----
        if (tile + NSM < NT64) issue(buf ^ 1, iaN, ibN);
        cp_commit();
        load_idx(tile + 2 * NSM, iaN, ibN);
        cp_wait1();                        // this tile's raw data ready

        // ---- Bias prefetch (LDGs hidden by convert + mainloop) ----
        float2 breg[2][4][2];
        #pragma unroll
        for (int mt = 0; mt < 2; ++mt)
            #pragma unroll
            for (int nt = 0; nt < 4; ++nt) {
                long r1 = row0 + wm * 32 + mt * 16 + gr;
                long r2 = r1 + 8;
                int  c  = wn * 32 + nt * 8 + gc;
                breg[mt][nt][0] = (r1 < NBb)
                    ? *(const float2*)(bias + (size_t)r1 * HH + c) : make_float2(0.f, 0.f);
                breg[mt][nt][1] = (r2 < NBb)
                    ? *(const float2*)(bias + (size_t)r2 * HH + c) : make_float2(0.f, 0.f);
            }

        // ---- Convert raw -> A planes (smem->smem, per-thread chunks) ----
        {
            const bool valid = (row0 + r) < NBb;
            const char* rawN = sm + OFS_RAW + buf * 65536 + r * 512;
            const char* rawM = rawN + 32768;
            #pragma unroll
            for (int i = 0; i < 4; ++i) {
                int q  = h + 4 * i;
                int c0 = 2 * q, c1 = 2 * q + 1;
                u32 s0 = (u32)((c0 ^ (r & 7)) * 16);
                u32 s1 = (u32)((c1 ^ (r & 7)) * 16);
                float4 x0 = *(const float4*)(rawN + s0);
                float4 x1 = *(const float4*)(rawN + s1);
                float4 y0 = *(const float4*)(rawM + s0);
                float4 y1 = *(const float4*)(rawM + s1);
                float v[8];
                v[0] = x0.x - y0.x; v[1] = x0.y - y0.y;
                v[2] = x0.z - y0.z; v[3] = x0.w - y0.w;
                v[4] = x1.x - y1.x; v[5] = x1.y - y1.y;
                v[6] = x1.z - y1.z; v[7] = x1.w - y1.w;
                if (!valid) {
                    #pragma unroll
                    for (int t = 0; t < 8; ++t) v[t] = 0.f;
                }
                u32 hi[4], lo[4];
                cvt8(v, hi, lo);
                int sw = (q ^ (r & 7)) * 16;
                *(uint4*)(sm + OFS_AHI + r * PITCHA + sw) = make_uint4(hi[0], hi[1], hi[2], hi[3]);
                *(uint4*)(sm + OFS_ALO + r * PITCHA + sw) = make_uint4(lo[0], lo[1], lo[2], lo[3]);
            }
        }
        __syncthreads();

        float acc[2][4][4];
        #pragma unroll
        for (int mt = 0; mt < 2; ++mt)
            #pragma unroll
            for (int nt = 0; nt < 4; ++nt)
                #pragma unroll
                for (int e = 0; e < 4; ++e) acc[mt][nt][e] = 0.f;

        mma_loop<PITCHA, 2, K_MSG / 16>(uAhi, uAlo, uB, uB + K_MSG * 256,
                                        acc, lane, wm, wn);
        __syncthreads();   // all LDSM done before next iter's convert

        // ---- Epilogue: relu(bias + acc) ----
        #pragma unroll
        for (int mt = 0; mt < 2; ++mt)
            #pragma unroll
            for (int nt = 0; nt < 4; ++nt) {
                long r1 = row0 + wm * 32 + mt * 16 + gr;
                long r2 = r1 + 8;
                int  c  = wn * 32 + nt * 8 + gc;
                const float* a = acc[mt][nt];
                if (r1 < NBb) {
                    float2 bb = breg[mt][nt][0];
                    *(float2*)(msg_out + (size_t)r1 * HH + c) =
                        make_float2(fmaxf(bb.x + a[0], 0.f), fmaxf(bb.y + a[1], 0.f));
                }
                if (r2 < NBb) {
                    float2 bb = breg[mt][nt][1];
                    *(float2*)(msg_out + (size_t)r2 * HH + c) =
                        make_float2(fmaxf(bb.x + a[2], 0.f), fmaxf(bb.y + a[3], 0.f));
                }
            }
    }
}

// ---------------------------------------------------------------------------
__global__ void __launch_bounds__(256) k_nei_agg(
    const float* __restrict__ msg, const int* __restrict__ a2nei,
    float* __restrict__ nei)
{
    const int warp = threadIdx.x >> 5, lane = threadIdx.x & 31;
    const int a = blockIdx.x * 8 + warp;
    if (a >= NAa) return;
    int idx[6];
    #pragma unroll
    for (int j = 0; j < 6; ++j) idx[j] = a2nei[a * 6 + j];
    float4 acc = make_float4(0.f, 0.f, 0.f, 0.f);
    #pragma unroll
    for (int j = 0; j < 6; ++j) {
        float4 v = *(const float4*)(msg + (long)idx[j] * HH + lane * 4);
        acc.x += v.x; acc.y += v.y; acc.z += v.z; acc.w += v.w;
    }
    *(float4*)(nei + (long)a * HH + lane * 4) = acc;
}

// ---------------------------------------------------------------------------
extern "C" void kernel_launch(void* const* d_in, const int* in_sizes, int n_in,
                              void* d_out, int out_size) {
    (void)in_sizes; (void)n_in; (void)out_size;

    const float* init_messages = (const float*)d_in[0];
    const float* attfea        = (const float*)d_in[1];
    const float* W_i           = (const float*)d_in[2];
    const float* W_h           = (const float*)d_in[3];  // [279][128]
    const int*   a2nei         = (const int*)d_in[4];
    const int*   a2att         = (const int*)d_in[5];
    const int*   b2a           = (const int*)d_in[6];
    const int*   b2revb        = (const int*)d_in[7];
    float*       out           = (float*)d_out;

    constexpr int SM_BIAS = 2 * (128 * 384) + K_WI * 512;   // 188416
    constexpr int SM_MSG  = 98304 + 2 * 65536;              // 229376 (224KB)

    cudaFuncSetAttribute(k_bias, cudaFuncAttributeMaxDynamicSharedMemorySize, SM_BIAS);
    cudaFuncSetAttribute(k_msg,  cudaFuncAttributeMaxDynamicSharedMemorySize, SM_MSG);

    float *bias, *m0, *m1, *nei, *attnei;
    cudaGetSymbolAddress((void**)&bias,   g_bias2);
    cudaGetSymbolAddress((void**)&m0,     g_msg0);
    cudaGetSymbolAddress((void**)&m1,     g_msg1);
    cudaGetSymbolAddress((void**)&nei,    g_nei);
    cudaGetSymbolAddress((void**)&attnei, g_attnei);

    const int gb128 = (NBb + 127) / 128;  // 3907

    // Launch 1: att aggregation + B-plane prep
    k_att_agg<<<GA + PREP_BLOCKS, 256>>>(attfea, a2att, attnei, W_i, W_h);
    // Launch 2: fused bias/inp kernel
    k_bias<<<gb128, 512, SM_BIAS>>>(init_messages, attnei, attfea,
                                    b2a, b2revb, bias, m0);

    // Launches 3..12: 5x (nei_agg, pipelined persistent msg GEMM). #4 = k_msg.
    float* cur = m0;
    float* nxt = m1;
    for (int it = 0; it < 5; ++it) {
        k_nei_agg<<<GA, 256>>>(cur, a2nei, nei);
        float* o = (it == 4) ? out : nxt;
        k_msg<<<NSM, 256, SM_MSG>>>(nei, cur, b2a, b2revb, bias, o);
        float* t = cur; cur = nxt; nxt = t;
    }
}

// round 16
// speedup vs baseline: 1.0744x; 1.0744x over previous
#include <cuda_runtime.h>
#include <cstdint>

// ---------------------------------------------------------------------------
// MPNEncoder, DEPTH=6, H=128 — bf16 hi/lo split GEMMs on legacy HMMA
// (mma.sync.m16n8k16.bf16; tcgen05 is PTX-gated off under compute_103).
//
//   attnei[a]  = sum_j attfea[a2attached[a,j]]             (once)
//   k_bias (fused, 2 phases sharing fp32 accum, 128-row tiles):
//     phase0: acc  = init_messages @ W_i ; msg0 = relu(acc)
//     phase1: acc += (attnei[b2a]-attfea[b2a_rev]) @ W_h[128:] ; bias = acc
//   5x: nei[a] = sum_j msg[a2nei[a,j]]
//       msg    = relu(bias + (nei[b2a] - msg[b2revb]) @ W_h[:128])
//
// R15: revert to the R13 best (persistent 2-CTA/SM k_msg, 128-row k_bias).
// R14's 1-CTA/SM cp.async pipeline regressed — the co-resident CTA already
// provides gather/MMA overlap.  Single tweak: next-tile index LDGs hoisted
// before the mainloop in k_msg.
// ---------------------------------------------------------------------------

constexpr int NBb  = 500000;
constexpr int NAa  = 250000;
constexpr int DMSG = 165;
constexpr int DATT = 151;
constexpr int HH   = 128;

constexpr int K_WI  = 176;
constexpr int K_ATT = 160;
constexpr int K_MSG = 128;
constexpr int BROWS = K_WI + K_ATT + K_MSG;          // 464

constexpr int NT64 = (NBb + 63) / 64;                // 7813 64-row tiles
constexpr int GMSG = 304;                            // 2 CTAs/SM

__device__ float g_bias2 [(size_t)NBb * HH];
__device__ float g_msg0  [(size_t)NBb * HH];
__device__ float g_msg1  [(size_t)NBb * HH];
__device__ float g_nei   [(size_t)NAa * HH];
__device__ float g_attnei[(size_t)NAa * DATT];
__device__ uint4 g_B     [BROWS * 32];               // 464*512 bytes

typedef unsigned int u32;

__device__ __forceinline__ u32 smem_u32(const void* p) {
    u32 a;
    asm("{ .reg .u64 t; cvta.to.shared.u64 t, %1; cvt.u32.u64 %0, t; }"
        : "=r"(a) : "l"(p));
    return a;
}
__device__ __forceinline__ void ldmx4(u32& r0, u32& r1, u32& r2, u32& r3, u32 addr) {
    asm volatile("ldmatrix.sync.aligned.m8n8.x4.shared.b16 {%0,%1,%2,%3}, [%4];"
                 : "=r"(r0), "=r"(r1), "=r"(r2), "=r"(r3) : "r"(addr));
}
__device__ __forceinline__ void ldmx4t(u32& r0, u32& r1, u32& r2, u32& r3, u32 addr) {
    asm volatile("ldmatrix.sync.aligned.m8n8.x4.trans.shared.b16 {%0,%1,%2,%3}, [%4];"
                 : "=r"(r0), "=r"(r1), "=r"(r2), "=r"(r3) : "r"(addr));
}
__device__ __forceinline__ void mma_bf16(float (&d)[4],
                                         u32 a0, u32 a1, u32 a2, u32 a3,
                                         u32 b0, u32 b1) {
    asm volatile("mma.sync.aligned.m16n8k16.row.col.f32.bf16.bf16.f32 "
                 "{%0,%1,%2,%3}, {%4,%5,%6,%7}, {%8,%9}, {%0,%1,%2,%3};"
                 : "+f"(d[0]), "+f"(d[1]), "+f"(d[2]), "+f"(d[3])
                 : "r"(a0), "r"(a1), "r"(a2), "r"(a3), "r"(b0), "r"(b1));
}
__device__ __forceinline__ void cpasync16(u32 dst, const void* src) {
    asm volatile("cp.async.cg.shared.global [%0], [%1], 16;"
                 :: "r"(dst), "l"(src));
}
__device__ __forceinline__ void cpasync_wait() {
    asm volatile("cp.async.commit_group;\ncp.async.wait_group 0;" ::: "memory");
}

// 8 floats -> 4 hi bf16x2 regs + 4 lo bf16x2 regs (low half = even index)
__device__ __forceinline__ void cvt8(const float* v, u32* hi, u32* lo) {
    #pragma unroll
    for (int i = 0; i < 4; ++i) {
        u32 u0 = __float_as_uint(v[2 * i])     & 0xffff0000u;
        u32 u1 = __float_as_uint(v[2 * i + 1]) & 0xffff0000u;
        hi[i] = u1 | (u0 >> 16);
        float l0 = v[2 * i]     - __uint_as_float(u0);
        float l1 = v[2 * i + 1] - __uint_as_float(u1);
        asm("cvt.rn.bf16x2.f32 %0, %1, %2;" : "=r"(lo[i]) : "f"(l1), "f"(l0));
    }
}

// Shared MMA mainloop.  Warp tile (MT*16) x 32; nt = 4.  Full unroll over NK.
template<int PITCHA, int MT, int NK>
__device__ __forceinline__ void mma_loop(
    u32 uAhi, u32 uAlo, u32 uBhi, u32 uBlo,
    float (&acc)[MT][4][4], int lane, int wm, int wn)
{
    const int aj   = lane >> 3;
    const int ai   = lane & 7;
    const int ajk  = aj >> 1;
    const int ajr  = (aj & 1) * 8;
    const int bkl  = lane & 15;
    const int bchl = lane >> 4;

    #pragma unroll 2
    for (int ks = 0; ks < NK; ++ks) {
        u32 ah[MT][4], al[MT][4];
        #pragma unroll
        for (int mt = 0; mt < MT; ++mt) {
            int arow = wm * (16 * MT) + mt * 16 + ajr + ai;
            int ch   = 2 * ks + ajk;
            u32 off  = (u32)(arow * PITCHA) + (u32)((ch ^ (arow & 7)) << 4);
            ldmx4(ah[mt][0], ah[mt][1], ah[mt][2], ah[mt][3], uAhi + off);
            ldmx4(al[mt][0], al[mt][1], al[mt][2], al[mt][3], uAlo + off);
        }
        u32 bh[4][2], bl[4][2];
        #pragma unroll
        for (int nt2 = 0; nt2 < 2; ++nt2) {
            int krow = ks * 16 + bkl;
            int ch   = wn * 4 + nt2 * 2 + bchl;
            u32 off  = (u32)(krow * 256) + (u32)((ch ^ (krow & 7)) << 4);
            u32 r0, r1, r2, r3;
            ldmx4t(r0, r1, r2, r3, uBhi + off);
            bh[2 * nt2][0] = r0; bh[2 * nt2][1] = r1;
            bh[2 * nt2 + 1][0] = r2; bh[2 * nt2 + 1][1] = r3;
            ldmx4t(r0, r1, r2, r3, uBlo + off);
            bl[2 * nt2][0] = r0; bl[2 * nt2][1] = r1;
            bl[2 * nt2 + 1][0] = r2; bl[2 * nt2 + 1][1] = r3;
        }
        #pragma unroll
        for (int mt = 0; mt < MT; ++mt)
            #pragma unroll
            for (int nt = 0; nt < 4; ++nt) {
                mma_bf16(acc[mt][nt], ah[mt][0], ah[mt][1], ah[mt][2], ah[mt][3],
                         bh[nt][0], bh[nt][1]);
                mma_bf16(acc[mt][nt], ah[mt][0], ah[mt][1], ah[mt][2], ah[mt][3],
                         bl[nt][0], bl[nt][1]);
                mma_bf16(acc[mt][nt], al[mt][0], al[mt][1], al[mt][2], al[mt][3],
                         bh[nt][0], bh[nt][1]);
            }
    }
}

// ---------------------------------------------------------------------------
// k_att_agg + B-plane prep (extra blocks).
// ---------------------------------------------------------------------------
constexpr int GA = NAa / 8;                              // 31250
constexpr int PREP_ITEMS  = BROWS * 16;
constexpr int PREP_BLOCKS = (PREP_ITEMS + 255) / 256;    // 29

__global__ void __launch_bounds__(256) k_att_agg(
    const float* __restrict__ attfea, const int* __restrict__ a2att,
    float* __restrict__ attnei,
    const float* __restrict__ W_i, const float* __restrict__ W_h)
{
    if (blockIdx.x >= GA) {
        int idx = (blockIdx.x - GA) * 256 + threadIdx.x;
        if (idx >= PREP_ITEMS) return;
        int r = idx >> 4, q = idx & 15;
        const float* src; unsigned char* dst; int k, Ksz, Kact;
        unsigned char* gb = (unsigned char*)g_B;
        if (r < K_WI) {
            k = r;           Ksz = K_WI;  Kact = DMSG; src = W_i;           dst = gb;
        } else if (r < K_WI + K_ATT) {
            k = r - K_WI;    Ksz = K_ATT; Kact = DATT; src = W_h + HH * HH; dst = gb + K_WI * 512;
        } else {
            k = r - K_WI - K_ATT; Ksz = K_MSG; Kact = HH; src = W_h;        dst = gb + (K_WI + K_ATT) * 512;
        }
        float v[8];
        #pragma unroll
        for (int t = 0; t < 8; ++t) {
            int c = q * 8 + t;
            v[t] = (k < Kact) ? src[(long)k * HH + c] : 0.f;
        }
        u32 hi[4], lo[4];
        cvt8(v, hi, lo);
        int sw = (q ^ (k & 7)) * 16;
        *(uint4*)(dst + k * 256 + sw)             = make_uint4(hi[0], hi[1], hi[2], hi[3]);
        *(uint4*)(dst + Ksz * 256 + k * 256 + sw) = make_uint4(lo[0], lo[1], lo[2], lo[3]);
        return;
    }

    const int warp = threadIdx.x >> 5, lane = threadIdx.x & 31;
    const int a = blockIdx.x * 8 + warp;
    if (a >= NAa) return;
    int idx[6];
    #pragma unroll
    for (int j = 0; j < 6; ++j) idx[j] = a2att[a * 6 + j];
    float acc[5] = {0.f, 0.f, 0.f, 0.f, 0.f};
    #pragma unroll
    for (int j = 0; j < 6; ++j) {
        const float* p = attfea + (long)idx[j] * DATT;
        #pragma unroll
        for (int t = 0; t < 5; ++t) {
            int c = t * 32 + lane;
            if (c < DATT) acc[t] += p[c];
        }
    }
    float* o = attnei + (long)a * DATT;
    #pragma unroll
    for (int t = 0; t < 5; ++t) {
        int c = t * 32 + lane;
        if (c < DATT) o[c] = acc[t];
    }
}

// ---------------------------------------------------------------------------
// FUSED bias kernel (R13 form): 128-row tile, 512 threads, warps 4(M)x4(N),
// warp tile 32x32 (MT=2).  Per-tile cp.async B copy overlapped with A gather.
// ---------------------------------------------------------------------------
__global__ void __launch_bounds__(512, 1) k_bias(
    const float* __restrict__ A0,     const float* __restrict__ attnei,
    const float* __restrict__ attfea, const int* __restrict__ b2a,
    const int* __restrict__ b2revb,
    float* __restrict__ bias_out, float* __restrict__ msg_out)
{
    constexpr int PITCHA = 384;

    extern __shared__ char sm[];
    char* pAhi = sm;                       // 128*384
    char* pAlo = sm + 128 * PITCHA;
    char* pBhi = sm + 2 * 128 * PITCHA;    // up to K_WI*512
    const u32 uAhi = smem_u32(pAhi);
    const u32 uAlo = smem_u32(pAlo);
    const u32 uBhi = smem_u32(pBhi);

    const int tid  = threadIdx.x;
    const int lane = tid & 31;
    const int warp = tid >> 5;
    const int wm   = warp & 3;
    const int wn   = warp >> 2;
    const long row0 = (long)blockIdx.x * 128;
    const unsigned char* gb = (const unsigned char*)g_B;

    float acc[2][4][4];
    #pragma unroll
    for (int mt = 0; mt < 2; ++mt)
        #pragma unroll
        for (int nt = 0; nt < 4; ++nt)
            #pragma unroll
            for (int e = 0; e < 4; ++e) acc[mt][nt][e] = 0.f;

    const int gr = lane >> 2;
    const int gc = (lane & 3) * 2;

    // ================= Phase 0: init_messages @ W_i (K=176) =================
    #pragma unroll
    for (int i = 0; i < 11; ++i) {
        int e = tid + i * 512;
        if (e < K_WI * 32) cpasync16(uBhi + e * 16, gb + e * 16);
    }
    {
        const int r = tid >> 2, h = tid & 3;
        const long b = row0 + r;
        const bool valid = b < NBb;
        const float* pA = A0 + (long)(valid ? b : 0) * DMSG;
        for (int q = h; q < K_WI / 8; q += 4) {
            float v[8];
            #pragma unroll
            for (int t = 0; t < 8; ++t) {
                int c = q * 8 + t;
                v[t] = (valid && c < DMSG) ? pA[c] : 0.f;
            }
            u32 hi[4], lo[4];
            cvt8(v, hi, lo);
            int sw = (q ^ (r & 7)) * 16;
            *(uint4*)(pAhi + r * PITCHA + sw) = make_uint4(hi[0], hi[1], hi[2], hi[3]);
            *(uint4*)(pAlo + r * PITCHA + sw) = make_uint4(lo[0], lo[1], lo[2], lo[3]);
        }
    }
    cpasync_wait();
    __syncthreads();
    mma_loop<PITCHA, 2, K_WI / 16>(uAhi, uAlo, uBhi, uBhi + K_WI * 256,
                                   acc, lane, wm, wn);

    // msg0 = relu(inp)
    #pragma unroll
    for (int mt = 0; mt < 2; ++mt)
        #pragma unroll
        for (int nt = 0; nt < 4; ++nt) {
            long r1 = row0 + wm * 32 + mt * 16 + gr;
            long r2 = r1 + 8;
            int  c  = wn * 32 + nt * 8 + gc;
            const float* a = acc[mt][nt];
            if (r1 < NBb)
                *(float2*)(msg_out + (size_t)r1 * HH + c) =
                    make_float2(fmaxf(a[0], 0.f), fmaxf(a[1], 0.f));
            if (r2 < NBb)
                *(float2*)(msg_out + (size_t)r2 * HH + c) =
                    make_float2(fmaxf(a[2], 0.f), fmaxf(a[3], 0.f));
        }
    __syncthreads();

    // ================= Phase 1: attdiff @ W_h[128:] (K=160) =================
    #pragma unroll
    for (int i = 0; i < 10; ++i) {
        int e = tid + i * 512;
        if (e < K_ATT * 32) cpasync16(uBhi + e * 16, gb + K_WI * 512 + e * 16);
    }
    {
        const int r = tid >> 2, h = tid & 3;
        const long b = row0 + r;
        const bool valid = b < NBb;
        const long bc = valid ? b : 0;
        int ia = b2a[bc];
        int ir = b2a[b2revb[bc]];
        const float* pA = attnei + (long)ia * DATT;
        const float* pR = attfea + (long)ir * DATT;
        for (int q = h; q < K_ATT / 8; q += 4) {
            float v[8];
            #pragma unroll
            for (int t = 0; t < 8; ++t) {
                int c = q * 8 + t;
                v[t] = (valid && c < DATT) ? (pA[c] - pR[c]) : 0.f;
            }
            u32 hi[4], lo[4];
            cvt8(v, hi, lo);
            int sw = (q ^ (r & 7)) * 16;
            *(uint4*)(pAhi + r * PITCHA + sw) = make_uint4(hi[0], hi[1], hi[2], hi[3]);
            *(uint4*)(pAlo + r * PITCHA + sw) = make_uint4(lo[0], lo[1], lo[2], lo[3]);
        }
    }
    cpasync_wait();
    __syncthreads();
    mma_loop<PITCHA, 2, K_ATT / 16>(uAhi, uAlo, uBhi, uBhi + K_ATT * 256,
                                    acc, lane, wm, wn);

    // bias = acc
    #pragma unroll
    for (int mt = 0; mt < 2; ++mt)
        #pragma unroll
        for (int nt = 0; nt < 4; ++nt) {
            long r1 = row0 + wm * 32 + mt * 16 + gr;
            long r2 = r1 + 8;
            int  c  = wn * 32 + nt * 8 + gc;
            const float* a = acc[mt][nt];
            if (r1 < NBb)
                *(float2*)(bias_out + (size_t)r1 * HH + c) = make_float2(a[0], a[1]);
            if (r2 < NBb)
                *(float2*)(bias_out + (size_t)r2 * HH + c) = make_float2(a[2], a[3]);
        }
}

// ---------------------------------------------------------------------------
// PERSISTENT MSG GEMM (R13 form): 64-row tiles, 256 threads, 8 warps (2Mx4N),
// smem 96KB -> 2 CTA/SM.  B copied once; bias prefetched to regs; next-tile
// index LDGs hoisted before the mainloop.
// ---------------------------------------------------------------------------
__global__ void __launch_bounds__(256, 2) k_msg(
    const float* __restrict__ nei, const float* __restrict__ msg_in,
    const int* __restrict__ b2a, const int* __restrict__ b2revb,
    const float* __restrict__ bias, float* __restrict__ msg_out)
{
    constexpr int PITCHA = 256;

    extern __shared__ char sm[];
    char* pAhi = sm;                        // 64*256
    char* pAlo = sm + 64 * PITCHA;
    char* pB   = sm + 2 * 64 * PITCHA;      // 128*512 (hi || lo)
    const u32 uAhi = smem_u32(pAhi);
    const u32 uAlo = smem_u32(pAlo);
    const u32 uB   = smem_u32(pB);

    const int tid  = threadIdx.x;
    const int lane = tid & 31;
    const int warp = tid >> 5;
    const int wm   = warp & 1;
    const int wn   = warp >> 1;
    const int r    = tid >> 2;              // row within tile
    const int h    = tid & 3;               // quarter within row
    const unsigned char* gb = (const unsigned char*)g_B + (K_WI + K_ATT) * 512;

    // Copy B once: 128*512 B = 4096 u4, 16/thread.
    #pragma unroll
    for (int i = 0; i < 16; ++i) {
        int e = tid + i * 256;
        cpasync16(uB + e * 16, gb + e * 16);
    }

    const int gr = lane >> 2;
    const int gc = (lane & 3) * 2;
    bool first = true;

    // Index prefetch for the first tile.
    const long tile0 = blockIdx.x;
    int ia, ib;
    {
        long b = tile0 * 64 + r;
        long bc = (b < NBb) ? b : 0;
        ia = b2a[bc];
        ib = b2revb[bc];
    }

    for (long tile = tile0; tile < NT64; tile += GMSG) {
        const long row0 = tile * 64;

        // ---- A fill: gather + subtract + split (uses prefetched ia/ib) ----
        {
            const bool valid = (row0 + r) < NBb;
            const float* pA = nei + (long)ia * HH;
            const float* pR = msg_in + (long)ib * HH;

            #pragma unroll
            for (int q = h; q < 16; q += 4) {
                float v[8];
                float4 x0 = ((const float4*)pA)[2 * q];
                float4 x1 = ((const float4*)pA)[2 * q + 1];
                float4 y0 = ((const float4*)pR)[2 * q];
                float4 y1 = ((const float4*)pR)[2 * q + 1];
                v[0] = x0.x - y0.x; v[1] = x0.y - y0.y;
                v[2] = x0.z - y0.z; v[3] = x0.w - y0.w;
                v[4] = x1.x - y1.x; v[5] = x1.y - y1.y;
                v[6] = x1.z - y1.z; v[7] = x1.w - y1.w;
                if (!valid) {
                    #pragma unroll
                    for (int t = 0; t < 8; ++t) v[t] = 0.f;
                }
                u32 hi[4], lo[4];
                cvt8(v, hi, lo);
                int sw = (q ^ (r & 7)) * 16;
                *(uint4*)(pAhi + r * PITCHA + sw) = make_uint4(hi[0], hi[1], hi[2], hi[3]);
                *(uint4*)(pAlo + r * PITCHA + sw) = make_uint4(lo[0], lo[1], lo[2], lo[3]);
            }
        }
        if (first) { cpasync_wait(); first = false; }
        __syncthreads();

        // ---- Prefetch next tile's indices (LDGs overlap the mainloop) ----
        {
            long bn = (tile + GMSG) * 64 + r;
            long bc = (tile + GMSG < NT64 && bn < NBb) ? bn : 0;
            ia = b2a[bc];
            ib = b2revb[bc];
        }

        // ---- Bias prefetch (LDGs issued pre-mainloop, consumed post) ----
        float2 breg[2][4][2];
        #pragma unroll
        for (int mt = 0; mt < 2; ++mt)
            #pragma unroll
            for (int nt = 0; nt < 4; ++nt) {
                long r1 = row0 + wm * 32 + mt * 16 + gr;
                long r2 = r1 + 8;
                int  c  = wn * 32 + nt * 8 + gc;
                breg[mt][nt][0] = (r1 < NBb)
                    ? *(const float2*)(bias + (size_t)r1 * HH + c) : make_float2(0.f, 0.f);
                breg[mt][nt][1] = (r2 < NBb)
                    ? *(const float2*)(bias + (size_t)r2 * HH + c) : make_float2(0.f, 0.f);
            }

        float acc[2][4][4];
        #pragma unroll
        for (int mt = 0; mt < 2; ++mt)
            #pragma unroll
            for (int nt = 0; nt < 4; ++nt)
                #pragma unroll
                for (int e = 0; e < 4; ++e) acc[mt][nt][e] = 0.f;

        mma_loop<PITCHA, 2, K_MSG / 16>(uAhi, uAlo, uB, uB + K_MSG * 256,
                                        acc, lane, wm, wn);
        __syncthreads();   // all LDSM done before next tile's A fill

        // ---- Epilogue: relu(bias + acc) ----
        #pragma unroll
        for (int mt = 0; mt < 2; ++mt)
            #pragma unroll
            for (int nt = 0; nt < 4; ++nt) {
                long r1 = row0 + wm * 32 + mt * 16 + gr;
                long r2 = r1 + 8;
                int  c  = wn * 32 + nt * 8 + gc;
                const float* a = acc[mt][nt];
                if (r1 < NBb) {
                    float2 bb = breg[mt][nt][0];
                    *(float2*)(msg_out + (size_t)r1 * HH + c) =
                        make_float2(fmaxf(bb.x + a[0], 0.f), fmaxf(bb.y + a[1], 0.f));
                }
                if (r2 < NBb) {
                    float2 bb = breg[mt][nt][1];
                    *(float2*)(msg_out + (size_t)r2 * HH + c) =
                        make_float2(fmaxf(bb.x + a[2], 0.f), fmaxf(bb.y + a[3], 0.f));
                }
            }
    }
}

// ---------------------------------------------------------------------------
__global__ void __launch_bounds__(256) k_nei_agg(
    const float* __restrict__ msg, const int* __restrict__ a2nei,
    float* __restrict__ nei)
{
    const int warp = threadIdx.x >> 5, lane = threadIdx.x & 31;
    const int a = blockIdx.x * 8 + warp;
    if (a >= NAa) return;
    int idx[6];
    #pragma unroll
    for (int j = 0; j < 6; ++j) idx[j] = a2nei[a * 6 + j];
    float4 acc = make_float4(0.f, 0.f, 0.f, 0.f);
    #pragma unroll
    for (int j = 0; j < 6; ++j) {
        float4 v = *(const float4*)(msg + (long)idx[j] * HH + lane * 4);
        acc.x += v.x; acc.y += v.y; acc.z += v.z; acc.w += v.w;
    }
    *(float4*)(nei + (long)a * HH + lane * 4) = acc;
}

// ---------------------------------------------------------------------------
extern "C" void kernel_launch(void* const* d_in, const int* in_sizes, int n_in,
                              void* d_out, int out_size) {
    (void)in_sizes; (void)n_in; (void)out_size;

    const float* init_messages = (const float*)d_in[0];
    const float* attfea        = (const float*)d_in[1];
    const float* W_i           = (const float*)d_in[2];
    const float* W_h           = (const float*)d_in[3];  // [279][128]
    const int*   a2nei         = (const int*)d_in[4];
    const int*   a2att         = (const int*)d_in[5];
    const int*   b2a           = (const int*)d_in[6];
    const int*   b2revb        = (const int*)d_in[7];
    float*       out           = (float*)d_out;

    constexpr int SM_BIAS = 2 * (128 * 384) + K_WI * 512;   // 188416
    constexpr int SM_MSG  = 2 * (64 * 256) + K_MSG * 512;   // 98304

    cudaFuncSetAttribute(k_bias, cudaFuncAttributeMaxDynamicSharedMemorySize, SM_BIAS);
    cudaFuncSetAttribute(k_msg,  cudaFuncAttributeMaxDynamicSharedMemorySize, SM_MSG);

    float *bias, *m0, *m1, *nei, *attnei;
    cudaGetSymbolAddress((void**)&bias,   g_bias2);
    cudaGetSymbolAddress((void**)&m0,     g_msg0);
    cudaGetSymbolAddress((void**)&m1,     g_msg1);
    cudaGetSymbolAddress((void**)&nei,    g_nei);
    cudaGetSymbolAddress((void**)&attnei, g_attnei);

    const int gb128 = (NBb + 127) / 128;  // 3907

    // Launch 1: att aggregation + B-plane prep
    k_att_agg<<<GA + PREP_BLOCKS, 256>>>(attfea, a2att, attnei, W_i, W_h);
    // Launch 2: fused bias/inp kernel
    k_bias<<<gb128, 512, SM_BIAS>>>(init_messages, attnei, attfea,
                                    b2a, b2revb, bias, m0);

    // Launches 3..12: 5x (nei_agg, persistent msg GEMM). #4 = first k_msg.
    float* cur = m0;
    float* nxt = m1;
    for (int it = 0; it < 5; ++it) {
        k_nei_agg<<<GA, 256>>>(cur, a2nei, nei);
        float* o = (it == 4) ? out : nxt;
        k_msg<<<GMSG, 256, SM_MSG>>>(nei, cur, b2a, b2revb, bias, o);
        float* t = cur; cur = nxt; nxt = t;
    }
}

// round 17
// speedup vs baseline: 1.0978x; 1.0217x over previous
#include <cuda_runtime.h>
#include <cstdint>

// ---------------------------------------------------------------------------
// MPNEncoder, DEPTH=6, H=128 — bf16 hi/lo split GEMMs on legacy HMMA
// (mma.sync.m16n8k16.bf16; tcgen05 is PTX-gated off under compute_103).
//
//   attnei[a]  = sum_j attfea[a2attached[a,j]]             (once)
//   k_bias (fused, 2 phases sharing fp32 accum):
//     phase0: acc  = init_messages @ W_i ; msg0 = relu(acc)
//     phase1: acc += (attnei[b2a]-attfea[b2a_rev]) @ W_h[128:] ; bias = acc
//   5x: nei[a] = sum_j msg[a2nei[a,j]]
//       msg    = relu(bias + (nei[b2a] - msg[b2revb]) @ W_h[:128])
//
// R16: k_bias rebuilt in the k_msg shape — 64-row tiles, 256 threads, MT=2,
// 96KB smem -> 2 CTA/SM — with B streamed through one 48KB buffer in
// 16k-aligned K-chunks (96+80 / 96+64).  k_msg unchanged (R15 best).
// ---------------------------------------------------------------------------

constexpr int NBb  = 500000;
constexpr int NAa  = 250000;
constexpr int DMSG = 165;
constexpr int DATT = 151;
constexpr int HH   = 128;

constexpr int K_WI  = 176;
constexpr int K_ATT = 160;
constexpr int K_MSG = 128;
constexpr int BROWS = K_WI + K_ATT + K_MSG;          // 464

constexpr int NT64 = (NBb + 63) / 64;                // 7813 64-row tiles
constexpr int GMSG = 304;                            // 2 CTAs/SM

__device__ float g_bias2 [(size_t)NBb * HH];
__device__ float g_msg0  [(size_t)NBb * HH];
__device__ float g_msg1  [(size_t)NBb * HH];
__device__ float g_nei   [(size_t)NAa * HH];
__device__ float g_attnei[(size_t)NAa * DATT];
__device__ uint4 g_B     [BROWS * 32];               // 464*512 bytes

typedef unsigned int u32;

__device__ __forceinline__ u32 smem_u32(const void* p) {
    u32 a;
    asm("{ .reg .u64 t; cvta.to.shared.u64 t, %1; cvt.u32.u64 %0, t; }"
        : "=r"(a) : "l"(p));
    return a;
}
__device__ __forceinline__ void ldmx4(u32& r0, u32& r1, u32& r2, u32& r3, u32 addr) {
    asm volatile("ldmatrix.sync.aligned.m8n8.x4.shared.b16 {%0,%1,%2,%3}, [%4];"
                 : "=r"(r0), "=r"(r1), "=r"(r2), "=r"(r3) : "r"(addr));
}
__device__ __forceinline__ void ldmx4t(u32& r0, u32& r1, u32& r2, u32& r3, u32 addr) {
    asm volatile("ldmatrix.sync.aligned.m8n8.x4.trans.shared.b16 {%0,%1,%2,%3}, [%4];"
                 : "=r"(r0), "=r"(r1), "=r"(r2), "=r"(r3) : "r"(addr));
}
__device__ __forceinline__ void mma_bf16(float (&d)[4],
                                         u32 a0, u32 a1, u32 a2, u32 a3,
                                         u32 b0, u32 b1) {
    asm volatile("mma.sync.aligned.m16n8k16.row.col.f32.bf16.bf16.f32 "
                 "{%0,%1,%2,%3}, {%4,%5,%6,%7}, {%8,%9}, {%0,%1,%2,%3};"
                 : "+f"(d[0]), "+f"(d[1]), "+f"(d[2]), "+f"(d[3])
                 : "r"(a0), "r"(a1), "r"(a2), "r"(a3), "r"(b0), "r"(b1));
}
__device__ __forceinline__ void cpasync16(u32 dst, const void* src) {
    asm volatile("cp.async.cg.shared.global [%0], [%1], 16;"
                 :: "r"(dst), "l"(src));
}
__device__ __forceinline__ void cpasync_wait() {
    asm volatile("cp.async.commit_group;\ncp.async.wait_group 0;" ::: "memory");
}

// 8 floats -> 4 hi bf16x2 regs + 4 lo bf16x2 regs (low half = even index)
__device__ __forceinline__ void cvt8(const float* v, u32* hi, u32* lo) {
    #pragma unroll
    for (int i = 0; i < 4; ++i) {
        u32 u0 = __float_as_uint(v[2 * i])     & 0xffff0000u;
        u32 u1 = __float_as_uint(v[2 * i + 1]) & 0xffff0000u;
        hi[i] = u1 | (u0 >> 16);
        float l0 = v[2 * i]     - __uint_as_float(u0);
        float l1 = v[2 * i + 1] - __uint_as_float(u1);
        asm("cvt.rn.bf16x2.f32 %0, %1, %2;" : "=r"(lo[i]) : "f"(l1), "f"(l0));
    }
}

// Shared MMA mainloop.  Warp tile (MT*16) x 32; nt = 4.  Full unroll over NK.
// kchunk0: base 16B-chunk index into the A planes (for K-split parts).
template<int PITCHA, int MT, int NK>
__device__ __forceinline__ void mma_loop(
    u32 uAhi, u32 uAlo, u32 uBhi, u32 uBlo,
    float (&acc)[MT][4][4], int lane, int wm, int wn, int kchunk0)
{
    const int aj   = lane >> 3;
    const int ai   = lane & 7;
    const int ajk  = aj >> 1;
    const int ajr  = (aj & 1) * 8;
    const int bkl  = lane & 15;
    const int bchl = lane >> 4;

    #pragma unroll 2
    for (int ks = 0; ks < NK; ++ks) {
        u32 ah[MT][4], al[MT][4];
        #pragma unroll
        for (int mt = 0; mt < MT; ++mt) {
            int arow = wm * (16 * MT) + mt * 16 + ajr + ai;
            int ch   = kchunk0 + 2 * ks + ajk;
            u32 off  = (u32)(arow * PITCHA) + (u32)((ch ^ (arow & 7)) << 4);
            ldmx4(ah[mt][0], ah[mt][1], ah[mt][2], ah[mt][3], uAhi + off);
            ldmx4(al[mt][0], al[mt][1], al[mt][2], al[mt][3], uAlo + off);
        }
        u32 bh[4][2], bl[4][2];
        #pragma unroll
        for (int nt2 = 0; nt2 < 2; ++nt2) {
            int krow = ks * 16 + bkl;
            int ch   = wn * 4 + nt2 * 2 + bchl;
            u32 off  = (u32)(krow * 256) + (u32)((ch ^ (krow & 7)) << 4);
            u32 r0, r1, r2, r3;
            ldmx4t(r0, r1, r2, r3, uBhi + off);
            bh[2 * nt2][0] = r0; bh[2 * nt2][1] = r1;
            bh[2 * nt2 + 1][0] = r2; bh[2 * nt2 + 1][1] = r3;
            ldmx4t(r0, r1, r2, r3, uBlo + off);
            bl[2 * nt2][0] = r0; bl[2 * nt2][1] = r1;
            bl[2 * nt2 + 1][0] = r2; bl[2 * nt2 + 1][1] = r3;
        }
        #pragma unroll
        for (int mt = 0; mt < MT; ++mt)
            #pragma unroll
            for (int nt = 0; nt < 4; ++nt) {
                mma_bf16(acc[mt][nt], ah[mt][0], ah[mt][1], ah[mt][2], ah[mt][3],
                         bh[nt][0], bh[nt][1]);
                mma_bf16(acc[mt][nt], ah[mt][0], ah[mt][1], ah[mt][2], ah[mt][3],
                         bl[nt][0], bl[nt][1]);
                mma_bf16(acc[mt][nt], al[mt][0], al[mt][1], al[mt][2], al[mt][3],
                         bh[nt][0], bh[nt][1]);
            }
    }
}

// ---------------------------------------------------------------------------
// k_att_agg + B-plane prep (extra blocks).
// ---------------------------------------------------------------------------
constexpr int GA = NAa / 8;                              // 31250
constexpr int PREP_ITEMS  = BROWS * 16;
constexpr int PREP_BLOCKS = (PREP_ITEMS + 255) / 256;    // 29

__global__ void __launch_bounds__(256) k_att_agg(
    const float* __restrict__ attfea, const int* __restrict__ a2att,
    float* __restrict__ attnei,
    const float* __restrict__ W_i, const float* __restrict__ W_h)
{
    if (blockIdx.x >= GA) {
        int idx = (blockIdx.x - GA) * 256 + threadIdx.x;
        if (idx >= PREP_ITEMS) return;
        int r = idx >> 4, q = idx & 15;
        const float* src; unsigned char* dst; int k, Ksz, Kact;
        unsigned char* gb = (unsigned char*)g_B;
        if (r < K_WI) {
            k = r;           Ksz = K_WI;  Kact = DMSG; src = W_i;           dst = gb;
        } else if (r < K_WI + K_ATT) {
            k = r - K_WI;    Ksz = K_ATT; Kact = DATT; src = W_h + HH * HH; dst = gb + K_WI * 512;
        } else {
            k = r - K_WI - K_ATT; Ksz = K_MSG; Kact = HH; src = W_h;        dst = gb + (K_WI + K_ATT) * 512;
        }
        float v[8];
        #pragma unroll
        for (int t = 0; t < 8; ++t) {
            int c = q * 8 + t;
            v[t] = (k < Kact) ? src[(long)k * HH + c] : 0.f;
        }
        u32 hi[4], lo[4];
        cvt8(v, hi, lo);
        int sw = (q ^ (k & 7)) * 16;
        *(uint4*)(dst + k * 256 + sw)             = make_uint4(hi[0], hi[1], hi[2], hi[3]);
        *(uint4*)(dst + Ksz * 256 + k * 256 + sw) = make_uint4(lo[0], lo[1], lo[2], lo[3]);
        return;
    }

    const int warp = threadIdx.x >> 5, lane = threadIdx.x & 31;
    const int a = blockIdx.x * 8 + warp;
    if (a >= NAa) return;
    int idx[6];
    #pragma unroll
    for (int j = 0; j < 6; ++j) idx[j] = a2att[a * 6 + j];
    float acc[5] = {0.f, 0.f, 0.f, 0.f, 0.f};
    #pragma unroll
    for (int j = 0; j < 6; ++j) {
        const float* p = attfea + (long)idx[j] * DATT;
        #pragma unroll
        for (int t = 0; t < 5; ++t) {
            int c = t * 32 + lane;
            if (c < DATT) acc[t] += p[c];
        }
    }
    float* o = attnei + (long)a * DATT;
    #pragma unroll
    for (int t = 0; t < 5; ++t) {
        int c = t * 32 + lane;
        if (c < DATT) o[c] = acc[t];
    }
}

// ---------------------------------------------------------------------------
// FUSED bias kernel (R16): 64-row tile, 256 threads, 8 warps (2M x 4N), MT=2.
// 96KB smem -> 2 CTA/SM.  B streamed through one 48KB buffer in K-chunks:
// phase0 (K=176): parts 96+80; phase1 (K=160): parts 96+64.
// ---------------------------------------------------------------------------
__global__ void __launch_bounds__(256, 2) k_bias(
    const float* __restrict__ A0,     const float* __restrict__ attnei,
    const float* __restrict__ attfea, const int* __restrict__ b2a,
    const int* __restrict__ b2revb,
    float* __restrict__ bias_out, float* __restrict__ msg_out)
{
    constexpr int PITCHA = 384;           // 24 chunks: fits NCH<=22 plus swizzle

    extern __shared__ char sm[];
    char* pAhi = sm;                       // 64*384 = 24576
    char* pAlo = sm + 64 * PITCHA;         // 24576
    char* pBuf = sm + 2 * 64 * PITCHA;     // 49152 (max part: 96 rows hi+lo)
    const u32 uAhi = smem_u32(pAhi);
    const u32 uAlo = smem_u32(pAlo);
    const u32 uBuf = smem_u32(pBuf);

    const int tid  = threadIdx.x;
    const int lane = tid & 31;
    const int warp = tid >> 5;
    const int wm   = warp & 1;
    const int wn   = warp >> 1;
    const int r    = tid >> 2;             // row in tile
    const int h    = tid & 3;              // quarter of row
    const long row0 = (long)blockIdx.x * 64;
    const long b    = row0 + r;
    const bool valid = b < NBb;
    const long bc   = valid ? b : 0;
    const unsigned char* gb  = (const unsigned char*)g_B;              // wi image
    const unsigned char* gbA = gb + 2 * K_WI * 256;                    // att image

    // Phase-1 gather indices prefetched now (LDGs overlap phase 0).
    const int ia = b2a[bc];
    const int ir = b2a[b2revb[bc]];

    // B-part copy: [hi pk rows || lo pk rows] contiguous into uBuf.
    auto copyB = [&](const unsigned char* srcHi, const unsigned char* srcLo, int pk) {
        int n = pk * 32;                   // uint4 count (both planes)
        for (int e = tid; e < n; e += 256) {
            const unsigned char* s = (e < pk * 16) ? srcHi + e * 16
                                                   : srcLo + (e - pk * 16) * 16;
            cpasync16(uBuf + e * 16, s);
        }
    };

    const int gr = lane >> 2;
    const int gc = (lane & 3) * 2;

    float acc[2][4][4];
    #pragma unroll
    for (int mt = 0; mt < 2; ++mt)
        #pragma unroll
        for (int nt = 0; nt < 4; ++nt)
            #pragma unroll
            for (int e = 0; e < 4; ++e) acc[mt][nt][e] = 0.f;

    // ================= Phase 0: init_messages @ W_i (K=176) =================
    copyB(gb, gb + K_WI * 256, 96);                     // part0: k 0..95
    {
        const float* pA = A0 + bc * DMSG;               // contiguous rows
        for (int q = h; q < 22; q += 4) {               // NCH = 22
            float v[8];
            #pragma unroll
            for (int t = 0; t < 8; ++t) {
                int c = q * 8 + t;
                v[t] = (valid && c < DMSG) ? pA[c] : 0.f;
            }
            u32 hi[4], lo[4];
            cvt8(v, hi, lo);
            int sw = (q ^ (r & 7)) * 16;
            *(uint4*)(pAhi + r * PITCHA + sw) = make_uint4(hi[0], hi[1], hi[2], hi[3]);
            *(uint4*)(pAlo + r * PITCHA + sw) = make_uint4(lo[0], lo[1], lo[2], lo[3]);
        }
    }
    cpasync_wait();
    __syncthreads();
    mma_loop<PITCHA, 2, 6>(uAhi, uAlo, uBuf, uBuf + 96 * 256,
                           acc, lane, wm, wn, 0);
    __syncthreads();

    copyB(gb + 96 * 256, gb + (K_WI + 96) * 256, 80);   // part1: k 96..175
    cpasync_wait();
    __syncthreads();
    mma_loop<PITCHA, 2, 5>(uAhi, uAlo, uBuf, uBuf + 80 * 256,
                           acc, lane, wm, wn, 12);
    __syncthreads();                                    // ldsm done -> A refill ok

    // msg0 = relu(inp)
    #pragma unroll
    for (int mt = 0; mt < 2; ++mt)
        #pragma unroll
        for (int nt = 0; nt < 4; ++nt) {
            long r1 = row0 + wm * 32 + mt * 16 + gr;
            long r2 = r1 + 8;
            int  c  = wn * 32 + nt * 8 + gc;
            const float* a = acc[mt][nt];
            if (r1 < NBb)
                *(float2*)(msg_out + (size_t)r1 * HH + c) =
                    make_float2(fmaxf(a[0], 0.f), fmaxf(a[1], 0.f));
            if (r2 < NBb)
                *(float2*)(msg_out + (size_t)r2 * HH + c) =
                    make_float2(fmaxf(a[2], 0.f), fmaxf(a[3], 0.f));
        }

    // ================= Phase 1: attdiff @ W_h[128:] (K=160) =================
    copyB(gbA, gbA + K_ATT * 256, 96);                  // part0: k 0..95
    {
        const float* pA = attnei + (long)ia * DATT;
        const float* pR = attfea + (long)ir * DATT;
        for (int q = h; q < 20; q += 4) {               // NCH = 20
            float v[8];
            #pragma unroll
            for (int t = 0; t < 8; ++t) {
                int c = q * 8 + t;
                v[t] = (valid && c < DATT) ? (pA[c] - pR[c]) : 0.f;
            }
            u32 hi[4], lo[4];
            cvt8(v, hi, lo);
            int sw = (q ^ (r & 7)) * 16;
            *(uint4*)(pAhi + r * PITCHA + sw) = make_uint4(hi[0], hi[1], hi[2], hi[3]);
            *(uint4*)(pAlo + r * PITCHA + sw) = make_uint4(lo[0], lo[1], lo[2], lo[3]);
        }
    }
    cpasync_wait();
    __syncthreads();
    mma_loop<PITCHA, 2, 6>(uAhi, uAlo, uBuf, uBuf + 96 * 256,
                           acc, lane, wm, wn, 0);
    __syncthreads();

    copyB(gbA + 96 * 256, gbA + (K_ATT + 96) * 256, 64); // part1: k 96..159
    cpasync_wait();
    __syncthreads();
    mma_loop<PITCHA, 2, 4>(uAhi, uAlo, uBuf, uBuf + 64 * 256,
                           acc, lane, wm, wn, 12);

    // bias = acc
    #pragma unroll
    for (int mt = 0; mt < 2; ++mt)
        #pragma unroll
        for (int nt = 0; nt < 4; ++nt) {
            long r1 = row0 + wm * 32 + mt * 16 + gr;
            long r2 = r1 + 8;
            int  c  = wn * 32 + nt * 8 + gc;
            const float* a = acc[mt][nt];
            if (r1 < NBb)
                *(float2*)(bias_out + (size_t)r1 * HH + c) = make_float2(a[0], a[1]);
            if (r2 < NBb)
                *(float2*)(bias_out + (size_t)r2 * HH + c) = make_float2(a[2], a[3]);
        }
}

// ---------------------------------------------------------------------------
// PERSISTENT MSG GEMM (R15 best, unchanged): 64-row tiles, 256 threads,
// 8 warps (2Mx4N), smem 96KB -> 2 CTA/SM.  B copied once; bias + next-tile
// index LDGs prefetched around the mainloop.
// ---------------------------------------------------------------------------
__global__ void __launch_bounds__(256, 2) k_msg(
    const float* __restrict__ nei, const float* __restrict__ msg_in,
    const int* __restrict__ b2a, const int* __restrict__ b2revb,
    const float* __restrict__ bias, float* __restrict__ msg_out)
{
    constexpr int PITCHA = 256;

    extern __shared__ char sm[];
    char* pAhi = sm;                        // 64*256
    char* pAlo = sm + 64 * PITCHA;
    char* pB   = sm + 2 * 64 * PITCHA;      // 128*512 (hi || lo)
    const u32 uAhi = smem_u32(pAhi);
    const u32 uAlo = smem_u32(pAlo);
    const u32 uB   = smem_u32(pB);

    const int tid  = threadIdx.x;
    const int lane = tid & 31;
    const int warp = tid >> 5;
    const int wm   = warp & 1;
    const int wn   = warp >> 1;
    const int r    = tid >> 2;
    const int h    = tid & 3;
    const unsigned char* gb = (const unsigned char*)g_B + (K_WI + K_ATT) * 512;

    #pragma unroll
    for (int i = 0; i < 16; ++i) {
        int e = tid + i * 256;
        cpasync16(uB + e * 16, gb + e * 16);
    }

    const int gr = lane >> 2;
    const int gc = (lane & 3) * 2;
    bool first = true;

    const long tile0 = blockIdx.x;
    int ia, ib;
    {
        long b = tile0 * 64 + r;
        long bc = (b < NBb) ? b : 0;
        ia = b2a[bc];
        ib = b2revb[bc];
    }

    for (long tile = tile0; tile < NT64; tile += GMSG) {
        const long row0 = tile * 64;

        {
            const bool valid = (row0 + r) < NBb;
            const float* pA = nei + (long)ia * HH;
            const float* pR = msg_in + (long)ib * HH;

            #pragma unroll
            for (int q = h; q < 16; q += 4) {
                float v[8];
                float4 x0 = ((const float4*)pA)[2 * q];
                float4 x1 = ((const float4*)pA)[2 * q + 1];
                float4 y0 = ((const float4*)pR)[2 * q];
                float4 y1 = ((const float4*)pR)[2 * q + 1];
                v[0] = x0.x - y0.x; v[1] = x0.y - y0.y;
                v[2] = x0.z - y0.z; v[3] = x0.w - y0.w;
                v[4] = x1.x - y1.x; v[5] = x1.y - y1.y;
                v[6] = x1.z - y1.z; v[7] = x1.w - y1.w;
                if (!valid) {
                    #pragma unroll
                    for (int t = 0; t < 8; ++t) v[t] = 0.f;
                }
                u32 hi[4], lo[4];
                cvt8(v, hi, lo);
                int sw = (q ^ (r & 7)) * 16;
                *(uint4*)(pAhi + r * PITCHA + sw) = make_uint4(hi[0], hi[1], hi[2], hi[3]);
                *(uint4*)(pAlo + r * PITCHA + sw) = make_uint4(lo[0], lo[1], lo[2], lo[3]);
            }
        }
        if (first) { cpasync_wait(); first = false; }
        __syncthreads();

        {
            long bn = (tile + GMSG) * 64 + r;
            long bc = (tile + GMSG < NT64 && bn < NBb) ? bn : 0;
            ia = b2a[bc];
            ib = b2revb[bc];
        }

        float2 breg[2][4][2];
        #pragma unroll
        for (int mt = 0; mt < 2; ++mt)
            #pragma unroll
            for (int nt = 0; nt < 4; ++nt) {
                long r1 = row0 + wm * 32 + mt * 16 + gr;
                long r2 = r1 + 8;
                int  c  = wn * 32 + nt * 8 + gc;
                breg[mt][nt][0] = (r1 < NBb)
                    ? *(const float2*)(bias + (size_t)r1 * HH + c) : make_float2(0.f, 0.f);
                breg[mt][nt][1] = (r2 < NBb)
                    ? *(const float2*)(bias + (size_t)r2 * HH + c) : make_float2(0.f, 0.f);
            }

        float acc[2][4][4];
        #pragma unroll
        for (int mt = 0; mt < 2; ++mt)
            #pragma unroll
            for (int nt = 0; nt < 4; ++nt)
                #pragma unroll
                for (int e = 0; e < 4; ++e) acc[mt][nt][e] = 0.f;

        mma_loop<PITCHA, 2, K_MSG / 16>(uAhi, uAlo, uB, uB + K_MSG * 256,
                                        acc, lane, wm, wn, 0);
        __syncthreads();

        #pragma unroll
        for (int mt = 0; mt < 2; ++mt)
            #pragma unroll
            for (int nt = 0; nt < 4; ++nt) {
                long r1 = row0 + wm * 32 + mt * 16 + gr;
                long r2 = r1 + 8;
                int  c  = wn * 32 + nt * 8 + gc;
                const float* a = acc[mt][nt];
                if (r1 < NBb) {
                    float2 bb = breg[mt][nt][0];
                    *(float2*)(msg_out + (size_t)r1 * HH + c) =
                        make_float2(fmaxf(bb.x + a[0], 0.f), fmaxf(bb.y + a[1], 0.f));
                }
                if (r2 < NBb) {
                    float2 bb = breg[mt][nt][1];
                    *(float2*)(msg_out + (size_t)r2 * HH + c) =
                        make_float2(fmaxf(bb.x + a[2], 0.f), fmaxf(bb.y + a[3], 0.f));
                }
            }
    }
}

// ---------------------------------------------------------------------------
__global__ void __launch_bounds__(256) k_nei_agg(
    const float* __restrict__ msg, const int* __restrict__ a2nei,
    float* __restrict__ nei)
{
    const int warp = threadIdx.x >> 5, lane = threadIdx.x & 31;
    const int a = blockIdx.x * 8 + warp;
    if (a >= NAa) return;
    int idx[6];
    #pragma unroll
    for (int j = 0; j < 6; ++j) idx[j] = a2nei[a * 6 + j];
    float4 acc = make_float4(0.f, 0.f, 0.f, 0.f);
    #pragma unroll
    for (int j = 0; j < 6; ++j) {
        float4 v = *(const float4*)(msg + (long)idx[j] * HH + lane * 4);
        acc.x += v.x; acc.y += v.y; acc.z += v.z; acc.w += v.w;
    }
    *(float4*)(nei + (long)a * HH + lane * 4) = acc;
}

// Dummy: keeps ncu aligned so launch #4 = k_bias (the changed kernel).
__global__ void k_dummy(float* p) { if (threadIdx.x == 0) p[0] = 0.f; }

// ---------------------------------------------------------------------------
extern "C" void kernel_launch(void* const* d_in, const int* in_sizes, int n_in,
                              void* d_out, int out_size) {
    (void)in_sizes; (void)n_in; (void)out_size;

    const float* init_messages = (const float*)d_in[0];
    const float* attfea        = (const float*)d_in[1];
    const float* W_i           = (const float*)d_in[2];
    const float* W_h           = (const float*)d_in[3];  // [279][128]
    const int*   a2nei         = (const int*)d_in[4];
    const int*   a2att         = (const int*)d_in[5];
    const int*   b2a           = (const int*)d_in[6];
    const int*   b2revb        = (const int*)d_in[7];
    float*       out           = (float*)d_out;

    constexpr int SM_BIAS = 2 * (64 * 384) + 96 * 512;   // 98304
    constexpr int SM_MSG  = 2 * (64 * 256) + K_MSG * 512; // 98304

    cudaFuncSetAttribute(k_bias, cudaFuncAttributeMaxDynamicSharedMemorySize, SM_BIAS);
    cudaFuncSetAttribute(k_msg,  cudaFuncAttributeMaxDynamicSharedMemorySize, SM_MSG);

    float *bias, *m0, *m1, *nei, *attnei;
    cudaGetSymbolAddress((void**)&bias,   g_bias2);
    cudaGetSymbolAddress((void**)&m0,     g_msg0);
    cudaGetSymbolAddress((void**)&m1,     g_msg1);
    cudaGetSymbolAddress((void**)&nei,    g_nei);
    cudaGetSymbolAddress((void**)&attnei, g_attnei);

    // Launch 1: att aggregation + B-plane prep
    k_att_agg<<<GA + PREP_BLOCKS, 256>>>(attfea, a2att, attnei, W_i, W_h);
    // Launches 2-3: dummies so ncu's profiled slot (#4) lands on k_bias.
    k_dummy<<<1, 32>>>(nei);
    k_dummy<<<1, 32>>>(nei);
    // Launch 4: fused bias/inp kernel (profiled)
    k_bias<<<NT64, 256, SM_BIAS>>>(init_messages, attnei, attfea,
                                   b2a, b2revb, bias, m0);

    // Launches 5..14: 5x (nei_agg, persistent msg GEMM).
    float* cur = m0;
    float* nxt = m1;
    for (int it = 0; it < 5; ++it) {
        k_nei_agg<<<GA, 256>>>(cur, a2nei, nei);
        float* o = (it == 4) ? out : nxt;
        k_msg<<<GMSG, 256, SM_MSG>>>(nei, cur, b2a, b2revb, bias, o);
        float* t = cur; cur = nxt; nxt = t;
    }
}